// round 16
// baseline (speedup 1.0000x reference)
#include <cuda_runtime.h>
#include <cuda_bf16.h>
#include <math.h>
#include <stdint.h>

#define B_   2
#define S_   1024
#define T_   2048
#define H_   1024
#define NH_  16
#define KV_  4
#define HD_  64
#define E_   16
#define F_   1024
#define TOPK 2
#define EPS_ 1e-6f

// ---------------- scratch (device globals; no allocation) ----------------
__device__ float d_qb[T_*NH_*HD_];
__device__ float d_kb[T_*KV_*HD_];
__device__ float d_vb[T_*KV_*HD_];
__device__ float d_x1[T_*H_];
__device__ float d_h2[T_*H_];
__device__ int   d_sel[T_*TOPK];
__device__ float d_rw[T_*TOPK];
__device__ int   d_cnt[E_];
__device__ int   d_off[E_];
__device__ int   d_pair[T_*TOPK];
__device__ int   d_tmap[64];
__device__ int   d_ntile[1];
__device__ float d_act[(size_t)T_*TOPK*F_];
__device__ float d_yb[(size_t)T_*TOPK*H_];

// bf16 weight / activation mirrors
__device__ __nv_bfloat16 b_qw[1024*1024];
__device__ __nv_bfloat16 b_kw[256*1024];
__device__ __nv_bfloat16 b_vw[256*1024];
__device__ __nv_bfloat16 b_ow[1024*1024];
__device__ __nv_bfloat16 b_wg[(size_t)E_*F_*H_];
__device__ __nv_bfloat16 b_wu[(size_t)E_*F_*H_];
__device__ __nv_bfloat16 b_wd[(size_t)E_*H_*F_];
__device__ __nv_bfloat16 b_h1[T_*H_];
__device__ __nv_bfloat16 b_h2[T_*H_];
__device__ __nv_bfloat16 b_ao[T_*NH_*HD_];
__device__ __nv_bfloat16 b_act[(size_t)T_*TOPK*F_];
__device__ __nv_bfloat16 b_kb16[T_*KV_*HD_];
__device__ __nv_bfloat16 b_vp[T_*KV_*HD_];

// ---------------- helpers ----------------
__device__ __forceinline__ uint32_t f2bf2(float lo, float hi) {
    __nv_bfloat162 h = __floats2bfloat162_rn(lo, hi);
    return *(uint32_t*)&h;
}
__device__ __forceinline__ void mma16(float* c, const uint32_t* a, const uint32_t* b) {
    asm volatile(
        "mma.sync.aligned.m16n8k16.row.col.f32.bf16.bf16.f32 "
        "{%0,%1,%2,%3}, {%4,%5,%6,%7}, {%8,%9}, {%0,%1,%2,%3};\n"
        : "+f"(c[0]), "+f"(c[1]), "+f"(c[2]), "+f"(c[3])
        : "r"(a[0]), "r"(a[1]), "r"(a[2]), "r"(a[3]), "r"(b[0]), "r"(b[1]));
}
__device__ __forceinline__ void ldsm4(uint32_t* r, uint32_t addr) {
    asm volatile("ldmatrix.sync.aligned.m8n8.x4.shared.b16 {%0,%1,%2,%3}, [%4];"
        : "=r"(r[0]), "=r"(r[1]), "=r"(r[2]), "=r"(r[3]) : "r"(addr));
}
__device__ __forceinline__ uint32_t sm_u32(const void* p) {
    return (uint32_t)__cvta_generic_to_shared(p);
}
__device__ __forceinline__ void cpa16(uint32_t dst, const void* src) {
    asm volatile("cp.async.ca.shared.global [%0], [%1], 16;" :: "r"(dst), "l"(src));
}
__device__ __forceinline__ void cpa16cg(uint32_t dst, const void* src) {
    asm volatile("cp.async.cg.shared.global [%0], [%1], 16;" :: "r"(dst), "l"(src));
}
__device__ __forceinline__ void cpa_commit() {
    asm volatile("cp.async.commit_group;" ::: "memory");
}
#define CPA_WAIT(n) asm volatile("cp.async.wait_group %0;" :: "n"(n) : "memory")

// 8 floats -> 8 bf16 per thread, grid-stride
__global__ void f2b_k(const float4* __restrict__ s, uint4* __restrict__ d, int n8) {
    int i = blockIdx.x * blockDim.x + threadIdx.x;
    int stride = gridDim.x * blockDim.x;
    for (; i < n8; i += stride) {
        float4 v0 = s[2*i];
        float4 v1 = s[2*i + 1];
        d[i] = make_uint4(f2bf2(v0.x, v0.y), f2bf2(v0.z, v0.w),
                          f2bf2(v1.x, v1.y), f2bf2(v1.z, v1.w));
    }
}

#define GEMM_DSMEM (98304 + 512 + 128)

// =======================================================================
// bf16 cp.async tensor-core GEMM — 3-stage pipeline, one sync per k-iter.
// Expert modes (2/3/4) read the compacted tile map.
// (round-13 verified kernel; loads switched to cp.async.cg)
// =======================================================================
__global__ __launch_bounds__(256, 2) void gemm_cp_k(
    int mode,
    const __nv_bfloat16* __restrict__ A,
    const __nv_bfloat16* __restrict__ B0,
    const __nv_bfloat16* __restrict__ B1,
    const __nv_bfloat16* __restrict__ B2,
    float* __restrict__ C0,
    float* __restrict__ C1,
    float* __restrict__ C2,
    __nv_bfloat16* __restrict__ Cb16,
    const float* __restrict__ res,
    const int* __restrict__ pair,
    const int* __restrict__ cnt,
    const int* __restrict__ off,
    const float* __restrict__ rw,
    const int* __restrict__ tmap,
    const int* __restrict__ ntile)
{
    extern __shared__ uint8_t dynraw[];
    const int tid = threadIdx.x;
    const int bn = blockIdx.x * 128;
    int e = blockIdx.z;
    int bm;

    int c_cnt = 0, o_off = 0;
    if (mode >= 2) {
        if (blockIdx.y >= ntile[0]) return;
        int tm = tmap[blockIdx.y];
        e = tm & 15;
        bm = (tm >> 4) << 7;
        c_cnt = cnt[e]; o_off = off[e];
    } else {
        bm = blockIdx.y * 128;
    }

    uint8_t* base = (uint8_t*)(((uintptr_t)dynraw + 127) & ~(uintptr_t)127);
    const uint32_t smb = sm_u32(base);
    int* rowtok = (int*)(base + 98304);

    const __nv_bfloat16* Bb;
    float* Cb = C0;
    int ldc = 1024, col0 = bn;
    if (mode == 0) {
        if (bn < 1024)      { Bb = B0 + (size_t)bn * 1024;          Cb = C0; ldc = 1024; col0 = bn; }
        else if (bn < 1280) { Bb = B1 + (size_t)(bn - 1024) * 1024; Cb = C1; ldc = 256;  col0 = bn - 1024; }
        else                { Bb = B2 + (size_t)(bn - 1280) * 1024; Cb = C2; ldc = 256;  col0 = bn - 1280; }
    } else {
        Bb = B0 + (size_t)e * (1024u * 1024u) + (size_t)bn * 1024;
    }

    if (mode == 2 || mode == 3) {
        if (tid < 128) {
            int r = bm + tid; if (r >= c_cnt) r = c_cnt - 1;
            rowtok[tid] = pair[o_off + r] >> 1;
        }
        __syncthreads();
    }

    const int row  = tid & 127;
    const int half = tid >> 7;
    const int rsw  = row & 7;
    const __nv_bfloat16* Arow;
    if (mode == 2 || mode == 3) {
        Arow = A + (size_t)rowtok[row] * 1024;
    } else if (mode == 4) {
        int r = bm + row; if (r >= c_cnt) r = c_cnt - 1;
        Arow = A + (size_t)(o_off + r) * 1024;
    } else {
        Arow = A + (size_t)(bm + row) * 1024;
    }
    const __nv_bfloat16* Brow = Bb + (size_t)row * 1024;

    uint32_t co[4];
    #pragma unroll
    for (int j = 0; j < 4; j++)
        co[j] = (uint32_t)(row * 128) + (uint32_t)((((half * 4 + j) ^ rsw)) << 4);

    #define GISSUE(it_, sn_) do { \
        const char* ga = (const char*)Arow + (it_) * 128 + half * 64; \
        const char* gb = (const char*)Brow + (it_) * 128 + half * 64; \
        uint32_t da = smb + (sn_) * 16384, db = smb + 49152 + (sn_) * 16384; \
        _Pragma("unroll") \
        for (int j = 0; j < 4; j++) { \
            cpa16cg(da + co[j], ga + j * 16); \
            cpa16cg(db + co[j], gb + j * 16); \
        } \
        cpa_commit(); \
    } while (0)

    const int lane = tid & 31;
    const int lc = lane & 3, lq = lane >> 2;
    const int warp = tid >> 5;
    const int m0 = (warp & 3) * 32;
    const int n0 = (warp >> 2) * 64;
    const int l7 = lane & 7;
    const uint32_t baseA = (uint32_t)((m0 + l7 + 8 * ((lane >> 3) & 1)) * 128);
    const uint32_t baseB = (uint32_t)((n0 + l7 + 8 * (lane >> 4)) * 128);
    const int csA = lane >> 4;
    const int csB = (lane >> 3) & 1;

    float acc[2][8][4] = {};

    GISSUE(0, 0);
    GISSUE(1, 1);

    const int NK = 16;
    for (int it = 0; it < NK; it++) {
        const int s = it % 3;
        if (it == NK - 1) { CPA_WAIT(0); } else { CPA_WAIT(1); }
        __syncthreads();

        const uint32_t sA = smb + s * 16384;
        const uint32_t sB = smb + 49152 + s * 16384;
        #pragma unroll
        for (int ks = 0; ks < 4; ks++) {
            uint32_t af[2][4], bf[4][4];
            int cA = ks * 2 + csA;
            uint32_t aad = sA + baseA + (uint32_t)(((cA ^ l7)) << 4);
            ldsm4(af[0], aad);
            ldsm4(af[1], aad + 2048);
            int cB = ks * 2 + csB;
            uint32_t bad = sB + baseB + (uint32_t)(((cB ^ l7)) << 4);
            #pragma unroll
            for (int p = 0; p < 4; p++)
                ldsm4(bf[p], bad + p * 2048);
            #pragma unroll
            for (int t = 0; t < 2; t++)
                #pragma unroll
                for (int u = 0; u < 8; u++)
                    mma16(acc[t][u], af[t], &bf[u >> 1][(u & 1) * 2]);
        }
        if (it + 2 < NK) GISSUE(it + 2, (it + 2) % 3);
    }

    #pragma unroll
    for (int t = 0; t < 2; t++) {
        #pragma unroll
        for (int hf = 0; hf < 2; hf++) {
            int ri = m0 + t*16 + lq + hf*8;
            int grow = bm + ri;
            if (mode >= 2 && grow >= c_cnt) continue;

            float wgt = 1.f;
            float* crow = nullptr;
            const float* gsrc = nullptr;
            __nv_bfloat16* brow = nullptr;
            if (mode == 0) {
                crow = Cb + (size_t)grow * ldc;
            } else if (mode == 1) {
                crow = Cb + (size_t)grow * 1024;
            } else if (mode == 2) {
                crow = C0 + (size_t)(o_off + grow) * 1024;
            } else if (mode == 3) {
                gsrc = res + (size_t)(o_off + grow) * 1024;
                brow = Cb16 + (size_t)(o_off + grow) * 1024;
            } else {
                int p = pair[o_off + grow];
                wgt = rw[p];
                crow = C0 + (size_t)p * 1024;
            }

            #pragma unroll
            for (int u = 0; u < 8; u++) {
                float v0 = acc[t][u][hf*2 + 0];
                float v1 = acc[t][u][hf*2 + 1];
                int col = col0 + n0 + u*8 + lc*2;
                if (mode == 1) {
                    const float* rr = res + (size_t)grow * 1024 + col;
                    v0 += rr[0]; v1 += rr[1];
                } else if (mode == 3) {
                    float2 g = *(const float2*)(gsrc + col);
                    v0 = g.x / (1.f + __expf(-g.x)) * v0;
                    v1 = g.y / (1.f + __expf(-g.y)) * v1;
                    *(uint32_t*)(brow + col) = f2bf2(v0, v1);
                    continue;
                } else if (mode == 4) {
                    v0 *= wgt; v1 *= wgt;
                }
                float2 o2; o2.x = v0; o2.y = v1;
                *(float2*)(crow + col) = o2;
            }
        }
    }
    #undef GISSUE
}

// =======================================================================
// bf16 flash attention — cp.async from pre-converted bf16 mirrors
// (unchanged — verified)
// =======================================================================
__global__ __launch_bounds__(128, 3) void attn_bf16_k(
    const float* __restrict__ Q, const __nv_bfloat16* __restrict__ Kb,
    const uint32_t* __restrict__ Vp, __nv_bfloat16* __restrict__ O)
{
    __shared__ uint32_t Ks[2][64][36];
    __shared__ uint32_t Vs[2][32][72];

    const int tid = threadIdx.x;
    const int warp = tid >> 5;
    const int lane = tid & 31;
    const int lq = lane >> 2, lc = lane & 3;
    const int bh = blockIdx.y;
    const int b = bh / NH_, h = bh % NH_, kvh = h >> 2;
    const int q0 = blockIdx.x * 64;
    const int m0 = warp * 16;

    const uint32_t ksb = sm_u32(&Ks[0][0][0]);
    const uint32_t vsb = sm_u32(&Vs[0][0][0]);

    #define AISSUE(k0_, st_) do { \
        _Pragma("unroll") \
        for (int i = 0; i < 4; i++) { \
            int c = tid + i * 128; \
            int kr = c >> 3, ko = c & 7; \
            cpa16(ksb + (st_) * 9216 + (uint32_t)(kr * 144 + ko * 16), \
                  (const char*)(Kb + ((size_t)(b*S_ + (k0_) + kr) * KV_ + kvh) * HD_) + ko * 16); \
            int vr = c >> 4, vo = c & 15; \
            cpa16(vsb + (st_) * 9216 + (uint32_t)(vr * 288 + vo * 16), \
                  (const char*)(Vp + ((size_t)(b*(S_/2) + ((k0_) >> 1) + vr) * KV_ + kvh) * HD_) + vo * 16); \
        } \
        cpa_commit(); \
    } while (0)

    uint32_t qf[4][4];
    {
        const float* Qr0 = Q + (size_t)(b*S_ + q0 + m0 + lq) * (NH_*HD_) + h * HD_;
        const float* Qr8 = Qr0 + 8 * (NH_*HD_);
        #pragma unroll
        for (int ks = 0; ks < 4; ks++) {
            float2 a0 = *(const float2*)(Qr0 + 16*ks + 2*lc);
            float2 a1 = *(const float2*)(Qr8 + 16*ks + 2*lc);
            float2 a2 = *(const float2*)(Qr0 + 16*ks + 8 + 2*lc);
            float2 a3 = *(const float2*)(Qr8 + 16*ks + 8 + 2*lc);
            qf[ks][0] = f2bf2(a0.x, a0.y);
            qf[ks][1] = f2bf2(a1.x, a1.y);
            qf[ks][2] = f2bf2(a2.x, a2.y);
            qf[ks][3] = f2bf2(a3.x, a3.y);
        }
    }

    float oacc[8][4] = {};
    float m_[2] = {-1e30f, -1e30f};
    float l_[2] = {0.f, 0.f};

    AISSUE(0, 0);

    for (int kt = 0; kt < 16; kt++) {
        const int s = kt & 1;
        if (kt + 1 < 16) { AISSUE((kt + 1) * 64, 1 - s); CPA_WAIT(1); }
        else             { CPA_WAIT(0); }
        __syncthreads();

        float sf[8][4] = {};
        #pragma unroll
        for (int ks = 0; ks < 4; ks++) {
            #pragma unroll
            for (int u = 0; u < 8; u++) {
                uint32_t bf[2];
                bf[0] = Ks[s][u*8 + lq][ks*8 + lc];
                bf[1] = Ks[s][u*8 + lq][ks*8 + lc + 4];
                mma16(sf[u], qf[ks], bf);
            }
        }

        #pragma unroll
        for (int g = 0; g < 2; g++) {
            float mx = -1e30f;
            #pragma unroll
            for (int u = 0; u < 8; u++) {
                sf[u][2*g]   *= 0.125f;
                sf[u][2*g+1] *= 0.125f;
                mx = fmaxf(mx, fmaxf(sf[u][2*g], sf[u][2*g+1]));
            }
            mx = fmaxf(mx, __shfl_xor_sync(0xffffffffu, mx, 1));
            mx = fmaxf(mx, __shfl_xor_sync(0xffffffffu, mx, 2));
            float mnew = fmaxf(m_[g], mx);
            float scl = __expf(m_[g] - mnew);
            float sum = 0.f;
            #pragma unroll
            for (int u = 0; u < 8; u++) {
                sf[u][2*g]   = __expf(sf[u][2*g]   - mnew);
                sf[u][2*g+1] = __expf(sf[u][2*g+1] - mnew);
                sum += sf[u][2*g] + sf[u][2*g+1];
            }
            sum += __shfl_xor_sync(0xffffffffu, sum, 1);
            sum += __shfl_xor_sync(0xffffffffu, sum, 2);
            l_[g] = l_[g] * scl + sum;
            m_[g] = mnew;
            #pragma unroll
            for (int u = 0; u < 8; u++) {
                oacc[u][2*g]   *= scl;
                oacc[u][2*g+1] *= scl;
            }
        }

        #pragma unroll
        for (int j = 0; j < 4; j++) {
            uint32_t af[4];
            af[0] = f2bf2(sf[2*j  ][0], sf[2*j  ][1]);
            af[1] = f2bf2(sf[2*j  ][2], sf[2*j  ][3]);
            af[2] = f2bf2(sf[2*j+1][0], sf[2*j+1][1]);
            af[3] = f2bf2(sf[2*j+1][2], sf[2*j+1][3]);
            #pragma unroll
            for (int u = 0; u < 8; u++) {
                uint32_t bf[2];
                bf[0] = Vs[s][8*j + lc    ][u*8 + lq];
                bf[1] = Vs[s][8*j + lc + 4][u*8 + lq];
                mma16(oacc[u], af, bf);
            }
        }
        __syncthreads();
    }
    #undef AISSUE

    #pragma unroll
    for (int g = 0; g < 2; g++) {
        float invl = 1.f / l_[g];
        __nv_bfloat16* orow = O + (size_t)(b*S_ + q0 + m0 + lq + 8*g) * (NH_*HD_) + h * HD_;
        #pragma unroll
        for (int u = 0; u < 8; u++) {
            *(uint32_t*)(orow + u*8 + lc*2) =
                f2bf2(oacc[u][2*g] * invl, oacc[u][2*g+1] * invl);
        }
    }
}

// ---------------- rmsnorm over H ----------------
__global__ void rmsnorm_k(const float* __restrict__ x, const float* __restrict__ w,
                          float* __restrict__ of, __nv_bfloat16* __restrict__ ob) {
    int t = blockIdx.x;
    const float* xr = x + (size_t)t * H_;
    float ss = 0.f;
    for (int i = threadIdx.x; i < H_; i += 256) { float v = xr[i]; ss += v * v; }
    __shared__ float red[256];
    red[threadIdx.x] = ss; __syncthreads();
    for (int s = 128; s > 0; s >>= 1) {
        if (threadIdx.x < s) red[threadIdx.x] += red[threadIdx.x + s];
        __syncthreads();
    }
    float inv = rsqrtf(red[0] / (float)H_ + EPS_);
    for (int i = threadIdx.x; i < H_; i += 256) {
        float v = xr[i] * inv * w[i];
        if (of) of[(size_t)t * H_ + i] = v;
        if (ob) ob[(size_t)t * H_ + i] = __float2bfloat16(v);
    }
}

// ---------------- q/k RMSNorm + RoPE + K/V bf16 mirror emission ----------
__global__ void qknorm_rope_k(float* __restrict__ q, const float* __restrict__ k,
                              const float* __restrict__ v,
                              const float* __restrict__ qn, const float* __restrict__ kn,
                              const int* __restrict__ pos,
                              __nv_bfloat16* __restrict__ kb16,
                              __nv_bfloat16* __restrict__ vp)
{
    int t = blockIdx.x;
    int w = threadIdx.x >> 5, lane = threadIdx.x & 31;
    float p = (float)pos[t];
    float invf = powf(10000.f, -(float)lane / 32.f);
    float ang = p * invf;
    float c = cosf(ang), s = sinf(ang);
    if (w < NH_) {
        float* base = q + (size_t)t * (NH_*HD_) + w * HD_;
        float x0 = base[lane], x1 = base[lane + 32];
        float ss = x0*x0 + x1*x1;
        #pragma unroll
        for (int o = 16; o > 0; o >>= 1) ss += __shfl_xor_sync(0xffffffffu, ss, o);
        float inv = rsqrtf(ss / 64.f + EPS_);
        float y0 = x0 * inv * qn[lane], y1 = x1 * inv * qn[lane + 32];
        base[lane]      = y0 * c - y1 * s;
        base[lane + 32] = y1 * c + y0 * s;
    }
    if (w < KV_) {
        const float* base = k + (size_t)t * (KV_*HD_) + w * HD_;
        float x0 = base[lane], x1 = base[lane + 32];
        float ss = x0*x0 + x1*x1;
        #pragma unroll
        for (int o = 16; o > 0; o >>= 1) ss += __shfl_xor_sync(0xffffffffu, ss, o);
        float inv = rsqrtf(ss / 64.f + EPS_);
        float y0 = x0 * inv * kn[lane], y1 = x1 * inv * kn[lane + 32];
        __nv_bfloat16* kout = kb16 + (size_t)t * (KV_*HD_) + w * HD_;
        kout[lane]      = __float2bfloat16(y0 * c - y1 * s);
        kout[lane + 32] = __float2bfloat16(y1 * c + y0 * s);
    }
    if (w >= 8 && w < 12) {
        int idx = (threadIdx.x - 256);             // 0..127 over warps 8-11
        #pragma unroll
        for (int rep = 0; rep < 2; rep++) {
            int vidx = idx * 2 + rep;              // 0..255
            int kvh = vidx >> 6, hd = vidx & 63;
            float val = v[(size_t)t * (KV_*HD_) + vidx];
            int bb = t >> 10, sPos = t & 1023;
            size_t u32i = ((size_t)(bb * (S_/2) + (sPos >> 1)) * KV_ + kvh) * HD_ + hd;
            vp[u32i * 2 + (sPos & 1)] = __float2bfloat16(val);
        }
    }
}

// ---------------- gate logits + cnt zeroing ----------------
__global__ void gate_k(const float* __restrict__ h2, const float* __restrict__ gw,
                       float* __restrict__ logits, int* __restrict__ cnt)
{
    int t = blockIdx.x;
    int w = threadIdx.x >> 5, lane = threadIdx.x & 31;
    if (t == 0 && threadIdx.x < E_) cnt[threadIdx.x] = 0;
    const float* xr = h2 + (size_t)t * H_;
    const float* gr = gw + (size_t)w * H_;
    float s = 0.f;
    for (int i = lane; i < H_; i += 32) s += xr[i] * gr[i];
    #pragma unroll
    for (int o = 16; o > 0; o >>= 1) s += __shfl_xor_sync(0xffffffffu, s, o);
    if (lane == 0) logits[(size_t)t * E_ + w] = s;
}

__global__ void route_k(const float* __restrict__ logits, int* __restrict__ sel,
                        float* __restrict__ rw, int* __restrict__ cnt)
{
    int t = blockIdx.x * blockDim.x + threadIdx.x;
    if (t >= T_) return;
    float l[E_];
    float mx = -1e30f;
    #pragma unroll
    for (int e = 0; e < E_; e++) { l[e] = logits[(size_t)t * E_ + e]; mx = fmaxf(mx, l[e]); }
    #pragma unroll
    for (int e = 0; e < E_; e++) l[e] = expf(l[e] - mx);
    int i1 = 0; float v1 = l[0];
    #pragma unroll
    for (int e = 1; e < E_; e++) if (l[e] > v1) { v1 = l[e]; i1 = e; }
    int i2 = -1; float v2 = -1.f;
    #pragma unroll
    for (int e = 0; e < E_; e++) if (e != i1 && l[e] > v2) { v2 = l[e]; i2 = e; }
    float inv = 1.f / (v1 + v2);
    sel[t*2]   = i1;  sel[t*2+1] = i2;
    rw[t*2]    = v1 * inv; rw[t*2+1] = v2 * inv;
    atomicAdd(&cnt[i1], 1);
    atomicAdd(&cnt[i2], 1);
}

// fused scan + scatter + tile-map build (single block)
__global__ void scansc_k(const int* __restrict__ cnt, int* __restrict__ off,
                         const int* __restrict__ sel, int* __restrict__ pair,
                         int* __restrict__ tmap, int* __restrict__ ntile)
{
    __shared__ int sfill[E_];
    if (threadIdx.x == 0) {
        int a = 0, n = 0;
        for (int e = 0; e < E_; e++) {
            off[e] = a; sfill[e] = a;
            int ce = cnt[e];
            for (int bm = 0; bm < ce; bm += 128) tmap[n++] = e | ((bm >> 7) << 4);
            a += ce;
        }
        ntile[0] = n;
    }
    __syncthreads();
    for (int p = threadIdx.x; p < T_ * TOPK; p += blockDim.x) {
        int e = sel[p];
        int pos = atomicAdd(&sfill[e], 1);
        pair[pos] = p;
    }
}

// ---------------- final: out = x1 + y0 + y1 (float4) ----------------
__global__ void final_k(const float4* __restrict__ x1, const float4* __restrict__ yb,
                        float4* __restrict__ out)
{
    int i = blockIdx.x * blockDim.x + threadIdx.x;
    if (i >= T_ * (H_/4)) return;
    int t = i / (H_/4), hh = i % (H_/4);
    float4 a  = x1[i];
    float4 y0 = yb[(size_t)(t*2)     * (H_/4) + hh];
    float4 y1 = yb[(size_t)(t*2 + 1) * (H_/4) + hh];
    float4 o;
    o.x = a.x + y0.x + y1.x;
    o.y = a.y + y0.y + y1.y;
    o.z = a.z + y0.z + y1.z;
    o.w = a.w + y0.w + y1.w;
    out[i] = o;
}

// ---------------- launcher ----------------
extern "C" void kernel_launch(void* const* d_in, const int* in_sizes, int n_in,
                              void* d_out, int out_size)
{
    const float* hs   = (const float*)d_in[0];
    const int*   pos  = (const int*)  d_in[1];
    const float* ln1  = (const float*)d_in[2];
    const float* ln2  = (const float*)d_in[3];
    const float* qw   = (const float*)d_in[4];
    const float* kw   = (const float*)d_in[5];
    const float* vw   = (const float*)d_in[6];
    const float* ow   = (const float*)d_in[7];
    const float* qn   = (const float*)d_in[8];
    const float* kn   = (const float*)d_in[9];
    const float* gw   = (const float*)d_in[10];
    const float* wgat = (const float*)d_in[11];
    const float* wup  = (const float*)d_in[12];
    const float* wdn  = (const float*)d_in[13];
    float* out        = (float*)d_out;
    float* out_logits = out + (size_t)T_ * H_;

    float *qb, *kb, *vb, *x1, *h2, *rw, *act, *yb;
    int *sel, *cnt, *off, *pair, *tmap, *ntile;
    __nv_bfloat16 *qwb, *kwb, *vwb, *owb, *wgb, *wub, *wdb, *h1b, *h2b, *aob, *actb, *kb16, *vp;
    cudaGetSymbolAddress((void**)&qb,  d_qb);
    cudaGetSymbolAddress((void**)&kb,  d_kb);
    cudaGetSymbolAddress((void**)&vb,  d_vb);
    cudaGetSymbolAddress((void**)&x1,  d_x1);
    cudaGetSymbolAddress((void**)&h2,  d_h2);
    cudaGetSymbolAddress((void**)&sel, d_sel);
    cudaGetSymbolAddress((void**)&rw,  d_rw);
    cudaGetSymbolAddress((void**)&cnt, d_cnt);
    cudaGetSymbolAddress((void**)&off, d_off);
    cudaGetSymbolAddress((void**)&pair,d_pair);
    cudaGetSymbolAddress((void**)&tmap,d_tmap);
    cudaGetSymbolAddress((void**)&ntile,d_ntile);
    cudaGetSymbolAddress((void**)&act, d_act);
    cudaGetSymbolAddress((void**)&yb,  d_yb);
    cudaGetSymbolAddress((void**)&qwb, b_qw);
    cudaGetSymbolAddress((void**)&kwb, b_kw);
    cudaGetSymbolAddress((void**)&vwb, b_vw);
    cudaGetSymbolAddress((void**)&owb, b_ow);
    cudaGetSymbolAddress((void**)&wgb, b_wg);
    cudaGetSymbolAddress((void**)&wub, b_wu);
    cudaGetSymbolAddress((void**)&wdb, b_wd);
    cudaGetSymbolAddress((void**)&h1b, b_h1);
    cudaGetSymbolAddress((void**)&h2b, b_h2);
    cudaGetSymbolAddress((void**)&aob, b_ao);
    cudaGetSymbolAddress((void**)&actb, b_act);
    cudaGetSymbolAddress((void**)&kb16, b_kb16);
    cudaGetSymbolAddress((void**)&vp,   b_vp);

    cudaFuncSetAttribute(gemm_cp_k, cudaFuncAttributeMaxDynamicSharedMemorySize, GEMM_DSMEM);

    static cudaStream_t s1 = nullptr, s2 = nullptr;
    static cudaEvent_t ev0 = nullptr, ev1 = nullptr, ev2 = nullptr;
    if (s1 == nullptr) {
        cudaStreamCreateWithFlags(&s1, cudaStreamNonBlocking);
        cudaStreamCreateWithFlags(&s2, cudaStreamNonBlocking);
        cudaEventCreateWithFlags(&ev0, cudaEventDisableTiming);
        cudaEventCreateWithFlags(&ev1, cudaEventDisableTiming);
        cudaEventCreateWithFlags(&ev2, cudaEventDisableTiming);
    }

    cudaEventRecord(ev0, 0);
    cudaStreamWaitEvent(s1, ev0, 0);
    cudaStreamWaitEvent(s2, ev0, 0);

    // s2: q/k/v weight conversion
    f2b_k<<<512, 256, 0, s2>>>((const float4*)qw, (uint4*)qwb, 1024*1024/8);
    f2b_k<<<128, 256, 0, s2>>>((const float4*)kw, (uint4*)kwb, 256*1024/8);
    f2b_k<<<128, 256, 0, s2>>>((const float4*)vw, (uint4*)vwb, 256*1024/8);
    cudaEventRecord(ev2, s2);

    // s1: o + expert weight conversions
    {
        int n8 = (int)((size_t)E_*F_*H_/8);
        f2b_k<<<512, 256, 0, s1>>>((const float4*)ow, (uint4*)owb, 1024*1024/8);
        f2b_k<<<4096, 256, 0, s1>>>((const float4*)wgat, (uint4*)wgb, n8);
        f2b_k<<<4096, 256, 0, s1>>>((const float4*)wup,  (uint4*)wub, n8);
        f2b_k<<<4096, 256, 0, s1>>>((const float4*)wdn,  (uint4*)wdb, n8);
    }
    cudaEventRecord(ev1, s1);

    // main path
    rmsnorm_k<<<T_, 256>>>(hs, ln1, nullptr, h1b);
    cudaStreamWaitEvent(0, ev2, 0);
    gemm_cp_k<<<dim3(12, 16, 1), 256, GEMM_DSMEM>>>(0, h1b, qwb, kwb, vwb, qb, kb, vb,
                                        nullptr, nullptr, nullptr, nullptr, nullptr, nullptr,
                                        nullptr, nullptr);
    qknorm_rope_k<<<T_, NH_*32>>>(qb, kb, vb, qn, kn, pos, kb16, vp);
    attn_bf16_k<<<dim3(S_/64, B_*NH_), 128>>>(qb, kb16, (const uint32_t*)vp, aob);
    cudaStreamWaitEvent(0, ev1, 0);
    gemm_cp_k<<<dim3(8, 16, 1), 256, GEMM_DSMEM>>>(1, aob, owb, nullptr, nullptr, x1, nullptr, nullptr,
                                        nullptr, hs, nullptr, nullptr, nullptr, nullptr,
                                        nullptr, nullptr);
    rmsnorm_k<<<T_, 256>>>(x1, ln2, h2, h2b);
    gate_k<<<T_, E_*32>>>(h2, gw, out_logits, cnt);
    route_k<<<(T_ + 255)/256, 256>>>(out_logits, sel, rw, cnt);
    scansc_k<<<1, 1024>>>(cnt, off, sel, pair, tmap, ntile);
    gemm_cp_k<<<dim3(8, 48, 1), 256, GEMM_DSMEM>>>(2, h2b, wgb, nullptr, nullptr, act, nullptr, nullptr,
                                        nullptr, nullptr, pair, cnt, off, rw, tmap, ntile);
    gemm_cp_k<<<dim3(8, 48, 1), 256, GEMM_DSMEM>>>(3, h2b, wub, nullptr, nullptr, nullptr, nullptr, nullptr,
                                        actb, act, pair, cnt, off, rw, tmap, ntile);
    gemm_cp_k<<<dim3(8, 48, 1), 256, GEMM_DSMEM>>>(4, actb, wdb, nullptr, nullptr, yb, nullptr, nullptr,
                                        nullptr, nullptr, pair, cnt, off, rw, tmap, ntile);
    final_k<<<(T_*(H_/4) + 255)/256, 256>>>((const float4*)x1, (const float4*)yb, (float4*)out);
}

// round 17
// speedup vs baseline: 1.1721x; 1.1721x over previous
#include <cuda_runtime.h>
#include <cuda_bf16.h>
#include <math.h>
#include <stdint.h>

#define B_   2
#define S_   1024
#define T_   2048
#define H_   1024
#define NH_  16
#define KV_  4
#define HD_  64
#define E_   16
#define F_   1024
#define TOPK 2
#define EPS_ 1e-6f

// ---------------- scratch (device globals; no allocation) ----------------
__device__ float d_qb[T_*NH_*HD_];
__device__ float d_kb[T_*KV_*HD_];
__device__ float d_vb[T_*KV_*HD_];
__device__ float d_x1[T_*H_];
__device__ float d_h2[T_*H_];
__device__ int   d_sel[T_*TOPK];
__device__ float d_rw[T_*TOPK];
__device__ int   d_cnt[E_];
__device__ int   d_off[E_];
__device__ int   d_pair[T_*TOPK];
__device__ int   d_tmap[64];
__device__ int   d_ntile[1];
__device__ float d_act[(size_t)T_*TOPK*F_];
__device__ float d_yb[(size_t)T_*TOPK*H_];

// bf16 weight / activation mirrors
__device__ __nv_bfloat16 b_qw[1024*1024];
__device__ __nv_bfloat16 b_kw[256*1024];
__device__ __nv_bfloat16 b_vw[256*1024];
__device__ __nv_bfloat16 b_ow[1024*1024];
__device__ __nv_bfloat16 b_wg[(size_t)E_*F_*H_];
__device__ __nv_bfloat16 b_wu[(size_t)E_*F_*H_];
__device__ __nv_bfloat16 b_wd[(size_t)E_*H_*F_];
__device__ __nv_bfloat16 b_h1[T_*H_];
__device__ __nv_bfloat16 b_h2[T_*H_];
__device__ __nv_bfloat16 b_ao[T_*NH_*HD_];
__device__ __nv_bfloat16 b_act[(size_t)T_*TOPK*F_];
__device__ __nv_bfloat16 b_kb16[T_*KV_*HD_];
__device__ __nv_bfloat16 b_vp[T_*KV_*HD_];

// ---------------- helpers ----------------
__device__ __forceinline__ uint32_t f2bf2(float lo, float hi) {
    __nv_bfloat162 h = __floats2bfloat162_rn(lo, hi);
    return *(uint32_t*)&h;
}
__device__ __forceinline__ void mma16(float* c, const uint32_t* a, const uint32_t* b) {
    asm volatile(
        "mma.sync.aligned.m16n8k16.row.col.f32.bf16.bf16.f32 "
        "{%0,%1,%2,%3}, {%4,%5,%6,%7}, {%8,%9}, {%0,%1,%2,%3};\n"
        : "+f"(c[0]), "+f"(c[1]), "+f"(c[2]), "+f"(c[3])
        : "r"(a[0]), "r"(a[1]), "r"(a[2]), "r"(a[3]), "r"(b[0]), "r"(b[1]));
}
__device__ __forceinline__ void ldsm4(uint32_t* r, uint32_t addr) {
    asm volatile("ldmatrix.sync.aligned.m8n8.x4.shared.b16 {%0,%1,%2,%3}, [%4];"
        : "=r"(r[0]), "=r"(r[1]), "=r"(r[2]), "=r"(r[3]) : "r"(addr));
}
__device__ __forceinline__ uint32_t sm_u32(const void* p) {
    return (uint32_t)__cvta_generic_to_shared(p);
}
__device__ __forceinline__ void cpa16(uint32_t dst, const void* src) {
    asm volatile("cp.async.ca.shared.global [%0], [%1], 16;" :: "r"(dst), "l"(src));
}
__device__ __forceinline__ void cpa_commit() {
    asm volatile("cp.async.commit_group;" ::: "memory");
}
#define CPA_WAIT(n) asm volatile("cp.async.wait_group %0;" :: "n"(n) : "memory")

// 8 floats -> 8 bf16 per thread, grid-stride
__global__ void f2b_k(const float4* __restrict__ s, uint4* __restrict__ d, int n8) {
    int i = blockIdx.x * blockDim.x + threadIdx.x;
    int stride = gridDim.x * blockDim.x;
    for (; i < n8; i += stride) {
        float4 v0 = s[2*i];
        float4 v1 = s[2*i + 1];
        d[i] = make_uint4(f2bf2(v0.x, v0.y), f2bf2(v0.z, v0.w),
                          f2bf2(v1.x, v1.y), f2bf2(v1.z, v1.w));
    }
}

#define GEMM_DSMEM (98304 + 512 + 128)

// =======================================================================
// bf16 cp.async tensor-core GEMM — 3-stage pipeline, one sync per k-iter.
// Expert modes (2/3/4) read the compacted tile map.
// (round-13 verified kernel, unchanged — cp.async.ca)
// =======================================================================
__global__ __launch_bounds__(256, 2) void gemm_cp_k(
    int mode,
    const __nv_bfloat16* __restrict__ A,
    const __nv_bfloat16* __restrict__ B0,
    const __nv_bfloat16* __restrict__ B1,
    const __nv_bfloat16* __restrict__ B2,
    float* __restrict__ C0,
    float* __restrict__ C1,
    float* __restrict__ C2,
    __nv_bfloat16* __restrict__ Cb16,
    const float* __restrict__ res,
    const int* __restrict__ pair,
    const int* __restrict__ cnt,
    const int* __restrict__ off,
    const float* __restrict__ rw,
    const int* __restrict__ tmap,
    const int* __restrict__ ntile)
{
    extern __shared__ uint8_t dynraw[];
    const int tid = threadIdx.x;
    const int bn = blockIdx.x * 128;
    int e = blockIdx.z;
    int bm;

    int c_cnt = 0, o_off = 0;
    if (mode >= 2) {
        if (blockIdx.y >= ntile[0]) return;
        int tm = tmap[blockIdx.y];
        e = tm & 15;
        bm = (tm >> 4) << 7;
        c_cnt = cnt[e]; o_off = off[e];
    } else {
        bm = blockIdx.y * 128;
    }

    uint8_t* base = (uint8_t*)(((uintptr_t)dynraw + 127) & ~(uintptr_t)127);
    const uint32_t smb = sm_u32(base);
    int* rowtok = (int*)(base + 98304);

    const __nv_bfloat16* Bb;
    float* Cb = C0;
    int ldc = 1024, col0 = bn;
    if (mode == 0) {
        if (bn < 1024)      { Bb = B0 + (size_t)bn * 1024;          Cb = C0; ldc = 1024; col0 = bn; }
        else if (bn < 1280) { Bb = B1 + (size_t)(bn - 1024) * 1024; Cb = C1; ldc = 256;  col0 = bn - 1024; }
        else                { Bb = B2 + (size_t)(bn - 1280) * 1024; Cb = C2; ldc = 256;  col0 = bn - 1280; }
    } else {
        Bb = B0 + (size_t)e * (1024u * 1024u) + (size_t)bn * 1024;
    }

    if (mode == 2 || mode == 3) {
        if (tid < 128) {
            int r = bm + tid; if (r >= c_cnt) r = c_cnt - 1;
            rowtok[tid] = pair[o_off + r] >> 1;
        }
        __syncthreads();
    }

    const int row  = tid & 127;
    const int half = tid >> 7;
    const int rsw  = row & 7;
    const __nv_bfloat16* Arow;
    if (mode == 2 || mode == 3) {
        Arow = A + (size_t)rowtok[row] * 1024;
    } else if (mode == 4) {
        int r = bm + row; if (r >= c_cnt) r = c_cnt - 1;
        Arow = A + (size_t)(o_off + r) * 1024;
    } else {
        Arow = A + (size_t)(bm + row) * 1024;
    }
    const __nv_bfloat16* Brow = Bb + (size_t)row * 1024;

    uint32_t co[4];
    #pragma unroll
    for (int j = 0; j < 4; j++)
        co[j] = (uint32_t)(row * 128) + (uint32_t)((((half * 4 + j) ^ rsw)) << 4);

    #define GISSUE(it_, sn_) do { \
        const char* ga = (const char*)Arow + (it_) * 128 + half * 64; \
        const char* gb = (const char*)Brow + (it_) * 128 + half * 64; \
        uint32_t da = smb + (sn_) * 16384, db = smb + 49152 + (sn_) * 16384; \
        _Pragma("unroll") \
        for (int j = 0; j < 4; j++) { \
            cpa16(da + co[j], ga + j * 16); \
            cpa16(db + co[j], gb + j * 16); \
        } \
        cpa_commit(); \
    } while (0)

    const int lane = tid & 31;
    const int lc = lane & 3, lq = lane >> 2;
    const int warp = tid >> 5;
    const int m0 = (warp & 3) * 32;
    const int n0 = (warp >> 2) * 64;
    const int l7 = lane & 7;
    const uint32_t baseA = (uint32_t)((m0 + l7 + 8 * ((lane >> 3) & 1)) * 128);
    const uint32_t baseB = (uint32_t)((n0 + l7 + 8 * (lane >> 4)) * 128);
    const int csA = lane >> 4;
    const int csB = (lane >> 3) & 1;

    float acc[2][8][4] = {};

    GISSUE(0, 0);
    GISSUE(1, 1);

    const int NK = 16;
    for (int it = 0; it < NK; it++) {
        const int s = it % 3;
        if (it == NK - 1) { CPA_WAIT(0); } else { CPA_WAIT(1); }
        __syncthreads();

        const uint32_t sA = smb + s * 16384;
        const uint32_t sB = smb + 49152 + s * 16384;
        #pragma unroll
        for (int ks = 0; ks < 4; ks++) {
            uint32_t af[2][4], bf[4][4];
            int cA = ks * 2 + csA;
            uint32_t aad = sA + baseA + (uint32_t)(((cA ^ l7)) << 4);
            ldsm4(af[0], aad);
            ldsm4(af[1], aad + 2048);
            int cB = ks * 2 + csB;
            uint32_t bad = sB + baseB + (uint32_t)(((cB ^ l7)) << 4);
            #pragma unroll
            for (int p = 0; p < 4; p++)
                ldsm4(bf[p], bad + p * 2048);
            #pragma unroll
            for (int t = 0; t < 2; t++)
                #pragma unroll
                for (int u = 0; u < 8; u++)
                    mma16(acc[t][u], af[t], &bf[u >> 1][(u & 1) * 2]);
        }
        if (it + 2 < NK) GISSUE(it + 2, (it + 2) % 3);
    }

    #pragma unroll
    for (int t = 0; t < 2; t++) {
        #pragma unroll
        for (int hf = 0; hf < 2; hf++) {
            int ri = m0 + t*16 + lq + hf*8;
            int grow = bm + ri;
            if (mode >= 2 && grow >= c_cnt) continue;

            float wgt = 1.f;
            float* crow = nullptr;
            const float* gsrc = nullptr;
            __nv_bfloat16* brow = nullptr;
            if (mode == 0) {
                crow = Cb + (size_t)grow * ldc;
            } else if (mode == 1) {
                crow = Cb + (size_t)grow * 1024;
            } else if (mode == 2) {
                crow = C0 + (size_t)(o_off + grow) * 1024;
            } else if (mode == 3) {
                gsrc = res + (size_t)(o_off + grow) * 1024;
                brow = Cb16 + (size_t)(o_off + grow) * 1024;
            } else {
                int p = pair[o_off + grow];
                wgt = rw[p];
                crow = C0 + (size_t)p * 1024;
            }

            #pragma unroll
            for (int u = 0; u < 8; u++) {
                float v0 = acc[t][u][hf*2 + 0];
                float v1 = acc[t][u][hf*2 + 1];
                int col = col0 + n0 + u*8 + lc*2;
                if (mode == 1) {
                    const float* rr = res + (size_t)grow * 1024 + col;
                    v0 += rr[0]; v1 += rr[1];
                } else if (mode == 3) {
                    float2 g = *(const float2*)(gsrc + col);
                    v0 = g.x / (1.f + __expf(-g.x)) * v0;
                    v1 = g.y / (1.f + __expf(-g.y)) * v1;
                    *(uint32_t*)(brow + col) = f2bf2(v0, v1);
                    continue;
                } else if (mode == 4) {
                    v0 *= wgt; v1 *= wgt;
                }
                float2 o2; o2.x = v0; o2.y = v1;
                *(float2*)(crow + col) = o2;
            }
        }
    }
    #undef GISSUE
}

// =======================================================================
// bf16 flash attention — cp.async from pre-converted bf16 mirrors
// (unchanged — verified)
// =======================================================================
__global__ __launch_bounds__(128, 3) void attn_bf16_k(
    const float* __restrict__ Q, const __nv_bfloat16* __restrict__ Kb,
    const uint32_t* __restrict__ Vp, __nv_bfloat16* __restrict__ O)
{
    __shared__ uint32_t Ks[2][64][36];
    __shared__ uint32_t Vs[2][32][72];

    const int tid = threadIdx.x;
    const int warp = tid >> 5;
    const int lane = tid & 31;
    const int lq = lane >> 2, lc = lane & 3;
    const int bh = blockIdx.y;
    const int b = bh / NH_, h = bh % NH_, kvh = h >> 2;
    const int q0 = blockIdx.x * 64;
    const int m0 = warp * 16;

    const uint32_t ksb = sm_u32(&Ks[0][0][0]);
    const uint32_t vsb = sm_u32(&Vs[0][0][0]);

    #define AISSUE(k0_, st_) do { \
        _Pragma("unroll") \
        for (int i = 0; i < 4; i++) { \
            int c = tid + i * 128; \
            int kr = c >> 3, ko = c & 7; \
            cpa16(ksb + (st_) * 9216 + (uint32_t)(kr * 144 + ko * 16), \
                  (const char*)(Kb + ((size_t)(b*S_ + (k0_) + kr) * KV_ + kvh) * HD_) + ko * 16); \
            int vr = c >> 4, vo = c & 15; \
            cpa16(vsb + (st_) * 9216 + (uint32_t)(vr * 288 + vo * 16), \
                  (const char*)(Vp + ((size_t)(b*(S_/2) + ((k0_) >> 1) + vr) * KV_ + kvh) * HD_) + vo * 16); \
        } \
        cpa_commit(); \
    } while (0)

    uint32_t qf[4][4];
    {
        const float* Qr0 = Q + (size_t)(b*S_ + q0 + m0 + lq) * (NH_*HD_) + h * HD_;
        const float* Qr8 = Qr0 + 8 * (NH_*HD_);
        #pragma unroll
        for (int ks = 0; ks < 4; ks++) {
            float2 a0 = *(const float2*)(Qr0 + 16*ks + 2*lc);
            float2 a1 = *(const float2*)(Qr8 + 16*ks + 2*lc);
            float2 a2 = *(const float2*)(Qr0 + 16*ks + 8 + 2*lc);
            float2 a3 = *(const float2*)(Qr8 + 16*ks + 8 + 2*lc);
            qf[ks][0] = f2bf2(a0.x, a0.y);
            qf[ks][1] = f2bf2(a1.x, a1.y);
            qf[ks][2] = f2bf2(a2.x, a2.y);
            qf[ks][3] = f2bf2(a3.x, a3.y);
        }
    }

    float oacc[8][4] = {};
    float m_[2] = {-1e30f, -1e30f};
    float l_[2] = {0.f, 0.f};

    AISSUE(0, 0);

    for (int kt = 0; kt < 16; kt++) {
        const int s = kt & 1;
        if (kt + 1 < 16) { AISSUE((kt + 1) * 64, 1 - s); CPA_WAIT(1); }
        else             { CPA_WAIT(0); }
        __syncthreads();

        float sf[8][4] = {};
        #pragma unroll
        for (int ks = 0; ks < 4; ks++) {
            #pragma unroll
            for (int u = 0; u < 8; u++) {
                uint32_t bf[2];
                bf[0] = Ks[s][u*8 + lq][ks*8 + lc];
                bf[1] = Ks[s][u*8 + lq][ks*8 + lc + 4];
                mma16(sf[u], qf[ks], bf);
            }
        }

        #pragma unroll
        for (int g = 0; g < 2; g++) {
            float mx = -1e30f;
            #pragma unroll
            for (int u = 0; u < 8; u++) {
                sf[u][2*g]   *= 0.125f;
                sf[u][2*g+1] *= 0.125f;
                mx = fmaxf(mx, fmaxf(sf[u][2*g], sf[u][2*g+1]));
            }
            mx = fmaxf(mx, __shfl_xor_sync(0xffffffffu, mx, 1));
            mx = fmaxf(mx, __shfl_xor_sync(0xffffffffu, mx, 2));
            float mnew = fmaxf(m_[g], mx);
            float scl = __expf(m_[g] - mnew);
            float sum = 0.f;
            #pragma unroll
            for (int u = 0; u < 8; u++) {
                sf[u][2*g]   = __expf(sf[u][2*g]   - mnew);
                sf[u][2*g+1] = __expf(sf[u][2*g+1] - mnew);
                sum += sf[u][2*g] + sf[u][2*g+1];
            }
            sum += __shfl_xor_sync(0xffffffffu, sum, 1);
            sum += __shfl_xor_sync(0xffffffffu, sum, 2);
            l_[g] = l_[g] * scl + sum;
            m_[g] = mnew;
            #pragma unroll
            for (int u = 0; u < 8; u++) {
                oacc[u][2*g]   *= scl;
                oacc[u][2*g+1] *= scl;
            }
        }

        #pragma unroll
        for (int j = 0; j < 4; j++) {
            uint32_t af[4];
            af[0] = f2bf2(sf[2*j  ][0], sf[2*j  ][1]);
            af[1] = f2bf2(sf[2*j  ][2], sf[2*j  ][3]);
            af[2] = f2bf2(sf[2*j+1][0], sf[2*j+1][1]);
            af[3] = f2bf2(sf[2*j+1][2], sf[2*j+1][3]);
            #pragma unroll
            for (int u = 0; u < 8; u++) {
                uint32_t bf[2];
                bf[0] = Vs[s][8*j + lc    ][u*8 + lq];
                bf[1] = Vs[s][8*j + lc + 4][u*8 + lq];
                mma16(oacc[u], af, bf);
            }
        }
        __syncthreads();
    }
    #undef AISSUE

    #pragma unroll
    for (int g = 0; g < 2; g++) {
        float invl = 1.f / l_[g];
        __nv_bfloat16* orow = O + (size_t)(b*S_ + q0 + m0 + lq + 8*g) * (NH_*HD_) + h * HD_;
        #pragma unroll
        for (int u = 0; u < 8; u++) {
            *(uint32_t*)(orow + u*8 + lc*2) =
                f2bf2(oacc[u][2*g] * invl, oacc[u][2*g+1] * invl);
        }
    }
}

// ---------------- rmsnorm over H (optional cnt zeroing) ----------------
__global__ void rmsnorm_k(const float* __restrict__ x, const float* __restrict__ w,
                          float* __restrict__ of, __nv_bfloat16* __restrict__ ob,
                          int* __restrict__ cnt) {
    int t = blockIdx.x;
    if (cnt && t == 0 && threadIdx.x < E_) cnt[threadIdx.x] = 0;
    const float* xr = x + (size_t)t * H_;
    float ss = 0.f;
    for (int i = threadIdx.x; i < H_; i += 256) { float v = xr[i]; ss += v * v; }
    __shared__ float red[256];
    red[threadIdx.x] = ss; __syncthreads();
    for (int s = 128; s > 0; s >>= 1) {
        if (threadIdx.x < s) red[threadIdx.x] += red[threadIdx.x + s];
        __syncthreads();
    }
    float inv = rsqrtf(red[0] / (float)H_ + EPS_);
    for (int i = threadIdx.x; i < H_; i += 256) {
        float v = xr[i] * inv * w[i];
        if (of) of[(size_t)t * H_ + i] = v;
        if (ob) ob[(size_t)t * H_ + i] = __float2bfloat16(v);
    }
}

// ---------------- q/k RMSNorm + RoPE + K/V bf16 mirror emission ----------
__global__ void qknorm_rope_k(float* __restrict__ q, const float* __restrict__ k,
                              const float* __restrict__ v,
                              const float* __restrict__ qn, const float* __restrict__ kn,
                              const int* __restrict__ pos,
                              __nv_bfloat16* __restrict__ kb16,
                              __nv_bfloat16* __restrict__ vp)
{
    int t = blockIdx.x;
    int w = threadIdx.x >> 5, lane = threadIdx.x & 31;
    float p = (float)pos[t];
    float invf = powf(10000.f, -(float)lane / 32.f);
    float ang = p * invf;
    float c = cosf(ang), s = sinf(ang);
    if (w < NH_) {
        float* base = q + (size_t)t * (NH_*HD_) + w * HD_;
        float x0 = base[lane], x1 = base[lane + 32];
        float ss = x0*x0 + x1*x1;
        #pragma unroll
        for (int o = 16; o > 0; o >>= 1) ss += __shfl_xor_sync(0xffffffffu, ss, o);
        float inv = rsqrtf(ss / 64.f + EPS_);
        float y0 = x0 * inv * qn[lane], y1 = x1 * inv * qn[lane + 32];
        base[lane]      = y0 * c - y1 * s;
        base[lane + 32] = y1 * c + y0 * s;
    }
    if (w < KV_) {
        const float* base = k + (size_t)t * (KV_*HD_) + w * HD_;
        float x0 = base[lane], x1 = base[lane + 32];
        float ss = x0*x0 + x1*x1;
        #pragma unroll
        for (int o = 16; o > 0; o >>= 1) ss += __shfl_xor_sync(0xffffffffu, ss, o);
        float inv = rsqrtf(ss / 64.f + EPS_);
        float y0 = x0 * inv * kn[lane], y1 = x1 * inv * kn[lane + 32];
        __nv_bfloat16* kout = kb16 + (size_t)t * (KV_*HD_) + w * HD_;
        kout[lane]      = __float2bfloat16(y0 * c - y1 * s);
        kout[lane + 32] = __float2bfloat16(y1 * c + y0 * s);
    }
    if (w >= 8 && w < 12) {
        int idx = (threadIdx.x - 256);             // 0..127 over warps 8-11
        #pragma unroll
        for (int rep = 0; rep < 2; rep++) {
            int vidx = idx * 2 + rep;              // 0..255
            int kvh = vidx >> 6, hd = vidx & 63;
            float val = v[(size_t)t * (KV_*HD_) + vidx];
            int bb = t >> 10, sPos = t & 1023;
            size_t u32i = ((size_t)(bb * (S_/2) + (sPos >> 1)) * KV_ + kvh) * HD_ + hd;
            vp[u32i * 2 + (sPos & 1)] = __float2bfloat16(val);
        }
    }
}

// ---------------- fused gate logits + softmax top-2 routing ----------------
// cnt is pre-zeroed by the preceding rmsnorm_k (kernel-boundary ordered).
__global__ void gate_route_k(const float* __restrict__ h2, const float* __restrict__ gw,
                             float* __restrict__ logits, int* __restrict__ sel,
                             float* __restrict__ rw, int* __restrict__ cnt)
{
    __shared__ float sl[E_];
    int t = blockIdx.x;
    int w = threadIdx.x >> 5, lane = threadIdx.x & 31;
    const float* xr = h2 + (size_t)t * H_;
    const float* gr = gw + (size_t)w * H_;
    float s = 0.f;
    for (int i = lane; i < H_; i += 32) s += xr[i] * gr[i];
    #pragma unroll
    for (int o = 16; o > 0; o >>= 1) s += __shfl_xor_sync(0xffffffffu, s, o);
    if (lane == 0) { logits[(size_t)t * E_ + w] = s; sl[w] = s; }
    __syncthreads();
    if (threadIdx.x == 0) {
        float l[E_];
        float mx = -1e30f;
        #pragma unroll
        for (int e = 0; e < E_; e++) { l[e] = sl[e]; mx = fmaxf(mx, l[e]); }
        #pragma unroll
        for (int e = 0; e < E_; e++) l[e] = expf(l[e] - mx);
        int i1 = 0; float v1 = l[0];
        #pragma unroll
        for (int e = 1; e < E_; e++) if (l[e] > v1) { v1 = l[e]; i1 = e; }
        int i2 = -1; float v2 = -1.f;
        #pragma unroll
        for (int e = 0; e < E_; e++) if (e != i1 && l[e] > v2) { v2 = l[e]; i2 = e; }
        float inv = 1.f / (v1 + v2);
        sel[t*2]   = i1;  sel[t*2+1] = i2;
        rw[t*2]    = v1 * inv; rw[t*2+1] = v2 * inv;
        atomicAdd(&cnt[i1], 1);
        atomicAdd(&cnt[i2], 1);
    }
}

// fused scan + scatter + tile-map build (single block)
__global__ void scansc_k(const int* __restrict__ cnt, int* __restrict__ off,
                         const int* __restrict__ sel, int* __restrict__ pair,
                         int* __restrict__ tmap, int* __restrict__ ntile)
{
    __shared__ int sfill[E_];
    if (threadIdx.x == 0) {
        int a = 0, n = 0;
        for (int e = 0; e < E_; e++) {
            off[e] = a; sfill[e] = a;
            int ce = cnt[e];
            for (int bm = 0; bm < ce; bm += 128) tmap[n++] = e | ((bm >> 7) << 4);
            a += ce;
        }
        ntile[0] = n;
    }
    __syncthreads();
    for (int p = threadIdx.x; p < T_ * TOPK; p += blockDim.x) {
        int e = sel[p];
        int pos = atomicAdd(&sfill[e], 1);
        pair[pos] = p;
    }
}

// ---------------- final: out = x1 + y0 + y1 (float4) ----------------
__global__ void final_k(const float4* __restrict__ x1, const float4* __restrict__ yb,
                        float4* __restrict__ out)
{
    int i = blockIdx.x * blockDim.x + threadIdx.x;
    if (i >= T_ * (H_/4)) return;
    int t = i / (H_/4), hh = i % (H_/4);
    float4 a  = x1[i];
    float4 y0 = yb[(size_t)(t*2)     * (H_/4) + hh];
    float4 y1 = yb[(size_t)(t*2 + 1) * (H_/4) + hh];
    float4 o;
    o.x = a.x + y0.x + y1.x;
    o.y = a.y + y0.y + y1.y;
    o.z = a.z + y0.z + y1.z;
    o.w = a.w + y0.w + y1.w;
    out[i] = o;
}

// ---------------- launcher ----------------
extern "C" void kernel_launch(void* const* d_in, const int* in_sizes, int n_in,
                              void* d_out, int out_size)
{
    const float* hs   = (const float*)d_in[0];
    const int*   pos  = (const int*)  d_in[1];
    const float* ln1  = (const float*)d_in[2];
    const float* ln2  = (const float*)d_in[3];
    const float* qw   = (const float*)d_in[4];
    const float* kw   = (const float*)d_in[5];
    const float* vw   = (const float*)d_in[6];
    const float* ow   = (const float*)d_in[7];
    const float* qn   = (const float*)d_in[8];
    const float* kn   = (const float*)d_in[9];
    const float* gw   = (const float*)d_in[10];
    const float* wgat = (const float*)d_in[11];
    const float* wup  = (const float*)d_in[12];
    const float* wdn  = (const float*)d_in[13];
    float* out        = (float*)d_out;
    float* out_logits = out + (size_t)T_ * H_;

    float *qb, *kb, *vb, *x1, *h2, *rw, *act, *yb;
    int *sel, *cnt, *off, *pair, *tmap, *ntile;
    __nv_bfloat16 *qwb, *kwb, *vwb, *owb, *wgb, *wub, *wdb, *h1b, *h2b, *aob, *actb, *kb16, *vp;
    cudaGetSymbolAddress((void**)&qb,  d_qb);
    cudaGetSymbolAddress((void**)&kb,  d_kb);
    cudaGetSymbolAddress((void**)&vb,  d_vb);
    cudaGetSymbolAddress((void**)&x1,  d_x1);
    cudaGetSymbolAddress((void**)&h2,  d_h2);
    cudaGetSymbolAddress((void**)&sel, d_sel);
    cudaGetSymbolAddress((void**)&rw,  d_rw);
    cudaGetSymbolAddress((void**)&cnt, d_cnt);
    cudaGetSymbolAddress((void**)&off, d_off);
    cudaGetSymbolAddress((void**)&pair,d_pair);
    cudaGetSymbolAddress((void**)&tmap,d_tmap);
    cudaGetSymbolAddress((void**)&ntile,d_ntile);
    cudaGetSymbolAddress((void**)&act, d_act);
    cudaGetSymbolAddress((void**)&yb,  d_yb);
    cudaGetSymbolAddress((void**)&qwb, b_qw);
    cudaGetSymbolAddress((void**)&kwb, b_kw);
    cudaGetSymbolAddress((void**)&vwb, b_vw);
    cudaGetSymbolAddress((void**)&owb, b_ow);
    cudaGetSymbolAddress((void**)&wgb, b_wg);
    cudaGetSymbolAddress((void**)&wub, b_wu);
    cudaGetSymbolAddress((void**)&wdb, b_wd);
    cudaGetSymbolAddress((void**)&h1b, b_h1);
    cudaGetSymbolAddress((void**)&h2b, b_h2);
    cudaGetSymbolAddress((void**)&aob, b_ao);
    cudaGetSymbolAddress((void**)&actb, b_act);
    cudaGetSymbolAddress((void**)&kb16, b_kb16);
    cudaGetSymbolAddress((void**)&vp,   b_vp);

    cudaFuncSetAttribute(gemm_cp_k, cudaFuncAttributeMaxDynamicSharedMemorySize, GEMM_DSMEM);

    static cudaStream_t s1 = nullptr, s2 = nullptr;
    static cudaEvent_t ev0 = nullptr, ev1 = nullptr, ev2 = nullptr;
    if (s1 == nullptr) {
        cudaStreamCreateWithFlags(&s1, cudaStreamNonBlocking);
        cudaStreamCreateWithFlags(&s2, cudaStreamNonBlocking);
        cudaEventCreateWithFlags(&ev0, cudaEventDisableTiming);
        cudaEventCreateWithFlags(&ev1, cudaEventDisableTiming);
        cudaEventCreateWithFlags(&ev2, cudaEventDisableTiming);
    }

    cudaEventRecord(ev0, 0);
    cudaStreamWaitEvent(s1, ev0, 0);
    cudaStreamWaitEvent(s2, ev0, 0);

    // s2: q/k/v weight conversion
    f2b_k<<<512, 256, 0, s2>>>((const float4*)qw, (uint4*)qwb, 1024*1024/8);
    f2b_k<<<128, 256, 0, s2>>>((const float4*)kw, (uint4*)kwb, 256*1024/8);
    f2b_k<<<128, 256, 0, s2>>>((const float4*)vw, (uint4*)vwb, 256*1024/8);
    cudaEventRecord(ev2, s2);

    // s1: o + expert weight conversions
    {
        int n8 = (int)((size_t)E_*F_*H_/8);
        f2b_k<<<512, 256, 0, s1>>>((const float4*)ow, (uint4*)owb, 1024*1024/8);
        f2b_k<<<4096, 256, 0, s1>>>((const float4*)wgat, (uint4*)wgb, n8);
        f2b_k<<<4096, 256, 0, s1>>>((const float4*)wup,  (uint4*)wub, n8);
        f2b_k<<<4096, 256, 0, s1>>>((const float4*)wdn,  (uint4*)wdb, n8);
    }
    cudaEventRecord(ev1, s1);

    // main path
    rmsnorm_k<<<T_, 256>>>(hs, ln1, nullptr, h1b, nullptr);
    cudaStreamWaitEvent(0, ev2, 0);
    gemm_cp_k<<<dim3(12, 16, 1), 256, GEMM_DSMEM>>>(0, h1b, qwb, kwb, vwb, qb, kb, vb,
                                        nullptr, nullptr, nullptr, nullptr, nullptr, nullptr,
                                        nullptr, nullptr);
    qknorm_rope_k<<<T_, NH_*32>>>(qb, kb, vb, qn, kn, pos, kb16, vp);
    attn_bf16_k<<<dim3(S_/64, B_*NH_), 128>>>(qb, kb16, (const uint32_t*)vp, aob);
    cudaStreamWaitEvent(0, ev1, 0);
    gemm_cp_k<<<dim3(8, 16, 1), 256, GEMM_DSMEM>>>(1, aob, owb, nullptr, nullptr, x1, nullptr, nullptr,
                                        nullptr, hs, nullptr, nullptr, nullptr, nullptr,
                                        nullptr, nullptr);
    rmsnorm_k<<<T_, 256>>>(x1, ln2, h2, h2b, cnt);
    gate_route_k<<<T_, E_*32>>>(h2, gw, out_logits, sel, rw, cnt);
    scansc_k<<<1, 1024>>>(cnt, off, sel, pair, tmap, ntile);
    gemm_cp_k<<<dim3(8, 48, 1), 256, GEMM_DSMEM>>>(2, h2b, wgb, nullptr, nullptr, act, nullptr, nullptr,
                                        nullptr, nullptr, pair, cnt, off, rw, tmap, ntile);
    gemm_cp_k<<<dim3(8, 48, 1), 256, GEMM_DSMEM>>>(3, h2b, wub, nullptr, nullptr, nullptr, nullptr, nullptr,
                                        actb, act, pair, cnt, off, rw, tmap, ntile);
    gemm_cp_k<<<dim3(8, 48, 1), 256, GEMM_DSMEM>>>(4, actb, wdb, nullptr, nullptr, yb, nullptr, nullptr,
                                        nullptr, nullptr, pair, cnt, off, rw, tmap, ntile);
    final_k<<<(T_*(H_/4) + 255)/256, 256>>>((const float4*)x1, (const float4*)yb, (float4*)out);
}